// round 2
// baseline (speedup 1.0000x reference)
#include <cuda_runtime.h>
#include <cstdint>

#define Bsz    4096
#define Tsteps 128
#define NLAT   256
#define NSt    64
#define NOut   32
#define Vterm  64
#define KB     8
#define MTILE  32

// Double-buffered latent state (2 x 4 MB). Static device memory (no allocs).
__device__ float g_xbuf[2][Bsz * NLAT];

// ---- packed f32x2 helpers ----
__device__ __forceinline__ unsigned long long pk2(float lo, float hi) {
    unsigned long long r;
    asm("mov.b64 %0, {%1, %2};" : "=l"(r) : "f"(lo), "f"(hi));
    return r;
}
__device__ __forceinline__ float2 upk2(unsigned long long v) {
    float2 r;
    asm("mov.b64 {%0, %1}, %2;" : "=f"(r.x), "=f"(r.y) : "l"(v));
    return r;
}
__device__ __forceinline__ void fma2(unsigned long long &d, unsigned long long a, unsigned long long b) {
    asm("fma.rn.f32x2 %0, %1, %2, %0;" : "+l"(d) : "l"(a), "l"(b));
}

// One fused LALR timestep:
//   x_new = tanh(x @ W1[s]^T + b1[s])
//   probs = softmax(x_new @ W2[s]^T + b2[s])
//   out[:, t, :] = scatter(probs at out_idx[s], last-write-wins)
__global__ void __launch_bounds__(256, 1) lalr_step(
    const float* __restrict__ latent0,
    const float* __restrict__ W1, const float* __restrict__ b1,
    const float* __restrict__ W2, const float* __restrict__ b2,
    const int*   __restrict__ state_seq, const int* __restrict__ out_idx,
    float* __restrict__ out, int tstep)
{
    extern __shared__ float sm[];
    float* xs   = sm;                    // [256][32]   x tile, k-major
    float* ws   = xs   + NLAT * MTILE;   // [2][8][256] W1 stage, k-major
    float* ws2t = ws   + 2 * KB * NLAT;  // [256][32]   W2 transposed (k-major)
    float* xn   = ws2t + NLAT * 32;      // [32][260]   x_new tile (padded)
    float* lg   = xn   + 32 * 260;       // [32][33]    logits (padded)
    float* yb   = lg   + 32 * 33;        // [8][64]     per-warp scatter buffer

    const int tid = threadIdx.x;
    const int s = state_seq[tstep];
    const float* W1s = W1 + (size_t)s * NLAT * NLAT;
    const float* W2s = W2 + (size_t)s * NOut * NLAT;
    const float* b1s = b1 + s * NLAT;
    const float* b2s = b2 + s * NOut;
    const float* xin = (tstep == 0) ? latent0 : g_xbuf[(tstep & 1) ^ 1];
    float* xoutg = g_xbuf[tstep & 1];
    const int rowbase = blockIdx.x * MTILE;

    // ---- load x tile into smem, k-major: xs[k][r] ----
    {
        int r  = tid >> 3;
        int kc = (tid & 7) * 32;
        const float* src = xin + (size_t)(rowbase + r) * NLAT + kc;
        #pragma unroll
        for (int i = 0; i < 8; i++) {
            float4 v = *(const float4*)(src + i * 4);
            int k0 = kc + i * 4;
            xs[(k0 + 0) * MTILE + r] = v.x;
            xs[(k0 + 1) * MTILE + r] = v.y;
            xs[(k0 + 2) * MTILE + r] = v.z;
            xs[(k0 + 3) * MTILE + r] = v.w;
        }
    }
    // ---- load W2[s] transposed into smem: ws2t[i][o] ----
    {
        int o  = tid & 31;
        int i0 = (tid >> 5) * 32;
        const float* src = W2s + (size_t)o * NLAT + i0;
        #pragma unroll
        for (int j = 0; j < 8; j++) {
            float4 v = *(const float4*)(src + j * 4);
            int i = i0 + j * 4;
            ws2t[(i + 0) * 32 + o] = v.x;
            ws2t[(i + 1) * 32 + o] = v.y;
            ws2t[(i + 2) * 32 + o] = v.z;
            ws2t[(i + 3) * 32 + o] = v.w;
        }
    }
    // ---- preload W1 K-stage 0 ----
    {
        const float* src = W1s + (size_t)tid * NLAT;
        float4 a  = *(const float4*)(src);
        float4 bq = *(const float4*)(src + 4);
        ws[0 * NLAT + tid] = a.x;  ws[1 * NLAT + tid] = a.y;
        ws[2 * NLAT + tid] = a.z;  ws[3 * NLAT + tid] = a.w;
        ws[4 * NLAT + tid] = bq.x; ws[5 * NLAT + tid] = bq.y;
        ws[6 * NLAT + tid] = bq.z; ws[7 * NLAT + tid] = bq.w;
    }
    __syncthreads();

    // ---- GEMM1: [32 x 256] x_new_pre = x @ W1^T ----
    const int warp = tid >> 5, lane = tid & 31;
    const int wr = warp >> 2, wc = warp & 3;
    const int csub = lane & 15, rsub = lane >> 4;
    const int c0 = wc * 64 + csub * 4;       // this lane's 4 columns
    const int rb = wr * 16 + rsub * 8;       // this lane's 8 rows (4 packed pairs)

    unsigned long long acc[4][4];
    #pragma unroll
    for (int p = 0; p < 4; p++)
        #pragma unroll
        for (int c = 0; c < 4; c++) acc[p][c] = 0ull;

    const int NT = NLAT / KB;  // 32 stages
    float4 na, nb;
    for (int kt = 0; kt < NT; kt++) {
        if (kt + 1 < NT) {
            const float* src = W1s + (size_t)tid * NLAT + (kt + 1) * KB;
            na = *(const float4*)(src);
            nb = *(const float4*)(src + 4);
        }
        const float* wsb = ws + (kt & 1) * KB * NLAT;
        const float* xsb = xs + (kt * KB) * MTILE + rb;
        #pragma unroll
        for (int kk = 0; kk < KB; kk++) {
            unsigned long long x0 = *(const unsigned long long*)(xsb + kk * MTILE + 0);
            unsigned long long x1 = *(const unsigned long long*)(xsb + kk * MTILE + 2);
            unsigned long long x2 = *(const unsigned long long*)(xsb + kk * MTILE + 4);
            unsigned long long x3 = *(const unsigned long long*)(xsb + kk * MTILE + 6);
            float4 w4 = *(const float4*)(wsb + kk * NLAT + c0);
            unsigned long long wA = pk2(w4.x, w4.x);
            unsigned long long wB = pk2(w4.y, w4.y);
            unsigned long long wC = pk2(w4.z, w4.z);
            unsigned long long wD = pk2(w4.w, w4.w);
            fma2(acc[0][0], x0, wA); fma2(acc[1][0], x1, wA);
            fma2(acc[2][0], x2, wA); fma2(acc[3][0], x3, wA);
            fma2(acc[0][1], x0, wB); fma2(acc[1][1], x1, wB);
            fma2(acc[2][1], x2, wB); fma2(acc[3][1], x3, wB);
            fma2(acc[0][2], x0, wC); fma2(acc[1][2], x1, wC);
            fma2(acc[2][2], x2, wC); fma2(acc[3][2], x3, wC);
            fma2(acc[0][3], x0, wD); fma2(acc[1][3], x1, wD);
            fma2(acc[2][3], x2, wD); fma2(acc[3][3], x3, wD);
        }
        if (kt + 1 < NT) {
            float* d = ws + ((kt + 1) & 1) * KB * NLAT;
            d[0 * NLAT + tid] = na.x; d[1 * NLAT + tid] = na.y;
            d[2 * NLAT + tid] = na.z; d[3 * NLAT + tid] = na.w;
            d[4 * NLAT + tid] = nb.x; d[5 * NLAT + tid] = nb.y;
            d[6 * NLAT + tid] = nb.z; d[7 * NLAT + tid] = nb.w;
            __syncthreads();
        }
    }

    // ---- epilogue: bias + tanh, write x_new to smem (xn) and global buffer ----
    {
        float4 bvec = *(const float4*)(b1s + c0);
        #pragma unroll
        for (int p = 0; p < 4; p++) {
            int r0 = rb + 2 * p;
            float2 u0 = upk2(acc[p][0]);
            float2 u1 = upk2(acc[p][1]);
            float2 u2 = upk2(acc[p][2]);
            float2 u3 = upk2(acc[p][3]);
            float4 rlo, rhi;
            rlo.x = tanhf(u0.x + bvec.x); rlo.y = tanhf(u1.x + bvec.y);
            rlo.z = tanhf(u2.x + bvec.z); rlo.w = tanhf(u3.x + bvec.w);
            rhi.x = tanhf(u0.y + bvec.x); rhi.y = tanhf(u1.y + bvec.y);
            rhi.z = tanhf(u2.y + bvec.z); rhi.w = tanhf(u3.y + bvec.w);
            *(float4*)(xn + r0 * 260 + c0)       = rlo;
            *(float4*)(xn + (r0 + 1) * 260 + c0) = rhi;
            *(float4*)(xoutg + (size_t)(rowbase + r0) * NLAT + c0)     = rlo;
            *(float4*)(xoutg + (size_t)(rowbase + r0 + 1) * NLAT + c0) = rhi;
        }
    }
    __syncthreads();

    // ---- GEMM2: logits[32 rows][32 outs] = x_new @ W2^T + b2 ----
    {
        int r2 = tid >> 3;
        int og = tid & 7;                 // 4 outputs: o = og*4 .. og*4+3
        const float* xrow  = xn + r2 * 260;
        const float* wbase = ws2t + og * 4;
        unsigned long long a0 = 0ull, a1 = 0ull, bb0 = 0ull, bb1 = 0ull;
        #pragma unroll 4
        for (int i = 0; i < NLAT; i += 2) {
            float xv0 = xrow[i], xv1 = xrow[i + 1];
            unsigned long long xx0 = pk2(xv0, xv0);
            unsigned long long xx1 = pk2(xv1, xv1);
            const unsigned long long* w0 = (const unsigned long long*)(wbase + i * 32);
            const unsigned long long* w1 = (const unsigned long long*)(wbase + (i + 1) * 32);
            fma2(a0,  xx0, w0[0]); fma2(a1,  xx0, w0[1]);
            fma2(bb0, xx1, w1[0]); fma2(bb1, xx1, w1[1]);
        }
        float2 A0 = upk2(a0), A1 = upk2(a1), B0 = upk2(bb0), B1 = upk2(bb1);
        int o0 = og * 4;
        lg[r2 * 33 + o0 + 0] = A0.x + B0.x + b2s[o0 + 0];
        lg[r2 * 33 + o0 + 1] = A0.y + B0.y + b2s[o0 + 1];
        lg[r2 * 33 + o0 + 2] = A1.x + B1.x + b2s[o0 + 2];
        lg[r2 * 33 + o0 + 3] = A1.y + B1.y + b2s[o0 + 3];
    }
    __syncthreads();

    // ---- softmax over 32 outputs + last-write-wins scatter into V=64 ----
    {
        float* y = yb + warp * 64;
        int idxv = out_idx[s * NOut + lane];
        unsigned mset  = __match_any_sync(0xffffffffu, idxv);
        bool   leader  = (31 - __clz(mset)) == lane;   // last occurrence wins
        #pragma unroll
        for (int rr = 0; rr < 4; rr++) {
            int row = warp * 4 + rr;
            float v = lg[row * 33 + lane];
            float m = v;
            #pragma unroll
            for (int off = 16; off > 0; off >>= 1)
                m = fmaxf(m, __shfl_xor_sync(0xffffffffu, m, off));
            float e = __expf(v - m);
            float ssum = e;
            #pragma unroll
            for (int off = 16; off > 0; off >>= 1)
                ssum += __shfl_xor_sync(0xffffffffu, ssum, off);
            float p = e / ssum;
            y[lane] = 0.f; y[lane + 32] = 0.f;
            __syncwarp();
            if (leader) y[idxv] = p;
            __syncwarp();
            float* op = out + (size_t)(rowbase + row) * (Tsteps * Vterm)
                            + (size_t)tstep * Vterm;
            op[lane]      = y[lane];
            op[lane + 32] = y[lane + 32];
            __syncwarp();
        }
    }
}

extern "C" void kernel_launch(void* const* d_in, const int* in_sizes, int n_in,
                              void* d_out, int out_size)
{
    const float* latent0   = (const float*)d_in[0];
    const float* W1        = (const float*)d_in[1];
    const float* b1        = (const float*)d_in[2];
    const float* W2        = (const float*)d_in[3];
    const float* b2        = (const float*)d_in[4];
    const int*   state_seq = (const int*)  d_in[5];
    const int*   out_idx   = (const int*)  d_in[6];
    float* out = (float*)d_out;

    // 8192+4096+8192+8320+1056+512 floats = 121472 bytes of dynamic smem
    const int smem_bytes = (NLAT * MTILE + 2 * KB * NLAT + NLAT * 32 +
                            32 * 260 + 32 * 33 + 8 * 64) * (int)sizeof(float);
    cudaFuncSetAttribute(lalr_step, cudaFuncAttributeMaxDynamicSharedMemorySize, smem_bytes);

    for (int t = 0; t < Tsteps; t++) {
        lalr_step<<<Bsz / MTILE, 256, smem_bytes>>>(
            latent0, W1, b1, W2, b2, state_seq, out_idx, out, t);
    }
}